// round 12
// baseline (speedup 1.0000x reference)
#include <cuda_runtime.h>
#include <cstdint>
#include <cstddef>

// Problem constants
#define BATCH 16384
#define F 512
#define CLUSTER 16       // one 16-CTA cluster (non-portable size), 1 GPC
#define TPB 512          // 16 warps; warp w owns columns b*32+2w, +1
#define SLOTS 4          // (epoch,value) slot ring; 2 suffice by dataflow

// Scratch (device globals: no allocation allowed in kernel_launch)
__device__ __align__(16) float g_xwz[(size_t)BATCH * F];   // x@Wz + bz
__device__ __align__(16) float g_xwh[(size_t)BATCH * F];   // x@Wh + bh

// ---------------------------------------------------------------------------
// PTX helpers
// ---------------------------------------------------------------------------
__device__ __forceinline__ uint32_t smem_u32(const void* p) {
    uint32_t a;
    asm("{ .reg .u64 t; cvta.to.shared.u64 t, %1; cvt.u32.u64 %0, t; }"
        : "=r"(a) : "l"(p));
    return a;
}
__device__ __forceinline__ unsigned long long fma2(
    unsigned long long a, unsigned long long b, unsigned long long c) {
    unsigned long long d;
    asm("fma.rn.f32x2 %0, %1, %2, %3;" : "=l"(d) : "l"(a), "l"(b), "l"(c));
    return d;
}
__device__ __forceinline__ unsigned long long add2(
    unsigned long long a, unsigned long long b) {
    unsigned long long d;
    asm("add.rn.f32x2 %0, %1, %2;" : "=l"(d) : "l"(a), "l"(b));
    return d;
}
__device__ __forceinline__ float pair_sum(unsigned long long p) {
    uint32_t lo, hi;
    asm("mov.b64 {%0, %1}, %2;" : "=r"(lo), "=r"(hi) : "l"(p));
    return __uint_as_float(lo) + __uint_as_float(hi);
}
__device__ __forceinline__ unsigned long long pack2f(float a0, float a1) {
    unsigned long long p;
    asm("mov.b64 %0, {%1, %2};" : "=l"(p)
        : "r"(__float_as_uint(a0)), "r"(__float_as_uint(a1)));
    return p;
}
__device__ __forceinline__ unsigned long long pack2u(uint32_t a0, uint32_t a1) {
    unsigned long long p;
    asm("mov.b64 %0, {%1, %2};" : "=l"(p) : "r"(a0), "r"(a1));
    return p;
}
__device__ __forceinline__ void unpack2(unsigned long long p,
                                        uint32_t& lo, uint32_t& hi) {
    asm("mov.b64 {%0, %1}, %2;" : "=r"(lo), "=r"(hi) : "l"(p));
}
__device__ __forceinline__ uint32_t mapa_rank(uint32_t laddr, int rank) {
    uint32_t r;
    asm("mapa.shared::cluster.u32 %0, %1, %2;" : "=r"(r) : "r"(laddr), "r"(rank));
    return r;
}
__device__ __forceinline__ void dsmem_store_u64(uint32_t raddr,
                                                unsigned long long v) {
    asm volatile("st.shared::cluster.u64 [%0], %1;"
                 :: "r"(raddr), "l"(v) : "memory");
}
__device__ __forceinline__ void lds_v2_u64(uint32_t addr,
                                           unsigned long long& a,
                                           unsigned long long& b) {
    asm volatile("ld.shared.v2.u64 {%0, %1}, [%2];"
                 : "=l"(a), "=l"(b) : "r"(addr));
}
__device__ __forceinline__ void cluster_arrive() {
    asm volatile("barrier.cluster.arrive.aligned;" ::: "memory");
}
__device__ __forceinline__ void cluster_wait() {
    asm volatile("barrier.cluster.wait.aligned;" ::: "memory");
}

// ---------------------------------------------------------------------------
// Phase 1: batched GEMM  C = A(16384x512) * W(512x512) + bias
// ---------------------------------------------------------------------------
#define BM 64
#define BN 64
#define BKK 16

__global__ void __launch_bounds__(256) gemm_kernel(
    const float* __restrict__ A,
    const float* __restrict__ Wz, const float* __restrict__ bz,
    const float* __restrict__ Wh, const float* __restrict__ bh)
{
    const float* B    = (blockIdx.z == 0) ? Wz : Wh;
    const float* bias = (blockIdx.z == 0) ? bz : bh;
    float*       C    = (blockIdx.z == 0) ? g_xwz : g_xwh;

    __shared__ float As[BKK][BM];
    __shared__ float Bs[BKK][BN];

    const int row0 = blockIdx.y * BM;
    const int col0 = blockIdx.x * BN;
    const int tid  = threadIdx.x;

    const int a_m = tid >> 2;
    const int a_k = (tid & 3) * 4;
    const int b_k = tid >> 4;
    const int b_n = (tid & 15) * 4;

    const int ty = tid >> 4;
    const int tx = tid & 15;

    float acc[4][4] = {};

    for (int k0 = 0; k0 < F; k0 += BKK) {
        float4 av = *(const float4*)(A + (size_t)(row0 + a_m) * F + k0 + a_k);
        As[a_k + 0][a_m] = av.x;
        As[a_k + 1][a_m] = av.y;
        As[a_k + 2][a_m] = av.z;
        As[a_k + 3][a_m] = av.w;
        float4 bv = *(const float4*)(B + (size_t)(k0 + b_k) * F + col0 + b_n);
        *(float4*)&Bs[b_k][b_n] = bv;
        __syncthreads();
#pragma unroll
        for (int k = 0; k < BKK; k++) {
            float ar[4], br[4];
            *(float4*)ar = *(const float4*)&As[k][ty * 4];
            *(float4*)br = *(const float4*)&Bs[k][tx * 4];
#pragma unroll
            for (int i = 0; i < 4; i++)
#pragma unroll
                for (int jj = 0; jj < 4; jj++)
                    acc[i][jj] = fmaf(ar[i], br[jj], acc[i][jj]);
        }
        __syncthreads();
    }

    float4 bv;
    bv.x = __ldg(&bias[col0 + tx * 4 + 0]);
    bv.y = __ldg(&bias[col0 + tx * 4 + 1]);
    bv.z = __ldg(&bias[col0 + tx * 4 + 2]);
    bv.w = __ldg(&bias[col0 + tx * 4 + 3]);
#pragma unroll
    for (int i = 0; i < 4; i++) {
        float4 o;
        o.x = acc[i][0] + bv.x;
        o.y = acc[i][1] + bv.y;
        o.z = acc[i][2] + bv.z;
        o.w = acc[i][3] + bv.w;
        *(float4*)(C + (size_t)(row0 + ty * 4 + i) * F + col0 + tx * 4) = o;
    }
}

// ---------------------------------------------------------------------------
// Phase 2: scan, one 16-CTA cluster, self-synchronizing (epoch,value) words
// with INCREMENTAL consumption (the R11 fix).
//
// Layout: CTA b owns columns b*32..+31; warp w owns cols 2w,2w+1; lane l
// handles column j0+(l>>4), state rows (l&15)*32..+31, register U (f32x2).
//
// Handoff: at step t every lane publishes ONE aligned 8-byte word
//     (epoch = t+1) << 32  |  bits(m_t[mycol])
// to rank hl's sval[t&3] slot (st.shared::cluster.u64: data IS readiness;
// one DSMEM hop; no barriers/flags/fences/syncthreads in the loop).
//
// Consumer (incremental): an unrolled pass attempts all not-yet-consumed
// chunks; a ready chunk is FMA'd IMMEDIATELY and marked in a bitmask (all
// register indices static). Repeat with a small FMA backoff until all lanes
// done. Effect: straggler waiting overlaps with FMA of arrived chunks, and
// poll traffic is only the missing 16B chunks (no full re-reads -> no R10
// livelock, lighter than R11).
//
// Slot-ring safety (SLOTS=4; 2 suffice): a warp writes step t only after
// consuming every producer's step t-1 words; each of those was published
// after its producer finished reading step t-2 -> readers of the
// overwritten slot are done. Gang-scheduled cluster, local-only polling.
// ---------------------------------------------------------------------------
__global__ void __launch_bounds__(TPB, 1) scan_kernel(
    const float* __restrict__ Uz,
    const float* __restrict__ Uh,
    float* __restrict__ out)
{
    __shared__ __align__(16) unsigned long long sval[SLOTS][F];  // 16 KB

    const int b = blockIdx.x;              // cluster rank
    const int w = threadIdx.x >> 5;
    const int l = threadIdx.x & 31;
    const int hw = l >> 4;
    const int hl = l & 15;                 // producer rank for this lane's rows
    const int mycol = b * 32 + w * 2 + hw;
    const int rbase = hl * 32;
    const bool head = (hl == 0);           // one writer of out[] per column

    // Zero all epochs (stale smem would alias old epochs across graph replays)
    for (int i = threadIdx.x; i < SLOTS * F; i += TPB)
        ((unsigned long long*)sval)[i] = 0ull;
    __syncthreads();
    cluster_arrive();                      // all CTAs' slots zeroed before use

    // Preload packed U slices (rows rbase+2i, rbase+2i+1 of column mycol)
    unsigned long long uzp[16], uhp[16];
#pragma unroll
    for (int i = 0; i < 16; i++) {
        uzp[i] = pack2f(Uz[(size_t)(rbase + 2 * i) * F + mycol],
                        Uz[(size_t)(rbase + 2 * i + 1) * F + mycol]);
        uhp[i] = pack2f(Uh[(size_t)(rbase + 2 * i) * F + mycol],
                        Uh[(size_t)(rbase + 2 * i + 1) * F + mycol]);
    }

    // Producer slot address for column mycol (bank-swizzled):
    // chunk jj of region rg lives at physical chunk rg*16+((jj&8)|((jj&7)^(rg&7)))
    const int Lc   = mycol >> 1;
    const int rg   = mycol >> 5;
    const int jj   = Lc & 15;
    const int phys = rg * 16 + ((jj & 8) | ((jj & 7) ^ (rg & 7)));
    const int s64  = phys * 2 + (mycol & 1);
    uint32_t dstv[SLOTS];
#pragma unroll
    for (int s = 0; s < SLOTS; s++)
        dstv[s] = mapa_rank(smem_u32(&sval[s][0]) + s64 * 8, hl);

    cluster_wait();

    float xz_p = __ldg(&g_xwz[mycol]);     // x@W terms for t = 0
    float xh_p = __ldg(&g_xwh[mycol]);
    float mj = 0.f;                        // m_{t-1}[mycol], register-carried
    float fill = (float)(threadIdx.x + 1) * 1.0e-18f;   // backoff chain carrier

    for (int t = 0; t < BATCH; t++) {
        unsigned long long az0 = 0ull, az1 = 0ull, ah0 = 0ull, ah1 = 0ull;

        if (t > 0) {
            const uint32_t slotbase =
                smem_u32(&sval[(t - 1) & (SLOTS - 1)][0]);
            const uint32_t tep = (uint32_t)t;          // expected epoch
            unsigned ready = 0u;                       // consumed-chunk bitmask
            int rounds = 0;
            for (;;) {
                // One pass: attempt every missing chunk; FMA it on arrival.
#pragma unroll
                for (int j = 0; j < 16; j++) {
                    if (!(ready & (1u << j))) {
                        const int pj = (j & 8) | ((j & 7) ^ (hl & 7));
                        const uint32_t addr = slotbase + ((hl * 16 + pj) << 4);
                        unsigned long long v0, v1;
                        lds_v2_u64(addr, v0, v1);
                        uint32_t lo0, hi0, lo1, hi1;
                        unpack2(v0, lo0, hi0);
                        unpack2(v1, lo1, hi1);
                        if (((hi0 ^ tep) | (hi1 ^ tep)) == 0u) {
                            const unsigned long long m01 = pack2u(lo0, lo1);
                            if (j & 1) {
                                az1 = fma2(m01, uzp[j], az1);
                                ah1 = fma2(m01, uhp[j], ah1);
                            } else {
                                az0 = fma2(m01, uzp[j], az0);
                                ah0 = fma2(m01, uhp[j], ah0);
                            }
                            ready |= (1u << j);
                        }
                    }
                }
                if (__all_sync(0xffffffffu, ready == 0xFFFFu)) break;
                // Small backoff: keeps poll pressure below delivery capacity.
#pragma unroll
                for (int i = 0; i < 8; i++)
                    fill = fmaf(fill, 1.0000001f, 1.0e-30f);
                if (++rounds > 64) { __nanosleep(200); rounds = 32; }
            }
        }

        float az = pair_sum(add2(az0, az1));
        float ah = pair_sum(add2(ah0, ah1));
        // 4-level butterfly inside the half-warp: sum lands in every lane
#pragma unroll
        for (int s = 8; s > 0; s >>= 1) {
            az += __shfl_xor_sync(0xffffffffu, az, s);
            ah += __shfl_xor_sync(0xffffffffu, ah, s);
        }

        // All lanes compute the gate (register-carried mj; no broadcast shfl)
        const float zp = az + xz_p;
        const float hp = ah + xh_p;
        const float z = __fdividef(1.f, 1.f + __expf(-zp));            // sigmoid
        const float h = 1.f - __fdividef(2.f, __expf(2.f * hp) + 1.f); // tanh
        const float mn = fmaf(z, h - mj, mj);

        if (head) out[(size_t)t * F + mycol] = mn;
        mj = mn;

        if (t + 1 < BATCH) {
            const unsigned long long pk =
                ((unsigned long long)(uint32_t)(t + 1) << 32) |
                (unsigned long long)__float_as_uint(mn);
            dsmem_store_u64(dstv[t & (SLOTS - 1)], pk);
            // Prefetch x@W for t+1 (off the critical path)
            xz_p = __ldg(&g_xwz[(size_t)(t + 1) * F + mycol]);
            xh_p = __ldg(&g_xwh[(size_t)(t + 1) * F + mycol]);
        }
    }

    // Keep the backoff chain live; condition can never hold.
    if (__float_as_uint(fill) == 0xdeadbeefu) out[0] = fill;

    // No CTA may exit while peers' DSMEM stores targeting it are in flight.
    cluster_arrive();
    cluster_wait();
}

// ---------------------------------------------------------------------------
// Launch: GEMMs -> single-cluster scan. All graph-capturable.
// ---------------------------------------------------------------------------
extern "C" void kernel_launch(void* const* d_in, const int* in_sizes, int n_in,
                              void* d_out, int out_size)
{
    const float* x  = (const float*)d_in[0];
    const float* Wz = (const float*)d_in[1];
    const float* Uz = (const float*)d_in[2];
    const float* bz = (const float*)d_in[3];
    const float* Wh = (const float*)d_in[4];
    const float* Uh = (const float*)d_in[5];
    const float* bh = (const float*)d_in[6];
    float* out = (float*)d_out;

    dim3 ggrid(F / BN, BATCH / BM, 2);   // 8 x 256 x 2
    gemm_kernel<<<ggrid, 256>>>(x, Wz, bz, Wh, bh);

    cudaFuncSetAttribute(scan_kernel,
                         cudaFuncAttributeNonPortableClusterSizeAllowed, 1);
    cudaLaunchConfig_t cfg = {};
    cfg.gridDim  = dim3(CLUSTER, 1, 1);
    cfg.blockDim = dim3(TPB, 1, 1);
    cfg.dynamicSmemBytes = 0;
    cfg.stream = 0;
    cudaLaunchAttribute attrs[1];
    attrs[0].id = cudaLaunchAttributeClusterDimension;
    attrs[0].val.clusterDim.x = CLUSTER;
    attrs[0].val.clusterDim.y = 1;
    attrs[0].val.clusterDim.z = 1;
    cfg.attrs = attrs;
    cfg.numAttrs = 1;
    cudaLaunchKernelEx(&cfg, scan_kernel, Uz, Uh, out);
}

// round 13
// speedup vs baseline: 1.3730x; 1.3730x over previous
#include <cuda_runtime.h>
#include <cstdint>
#include <cstddef>

// Problem constants
#define BATCH 16384
#define F 512
#define CLUSTER 16       // one 16-CTA cluster (non-portable size), 1 GPC
#define TPB 512          // 16 warps; warp w owns columns b*32+2w, +1
#define SLOTS 4          // state slot ring (2 suffice; 4 for margin)

// Scratch (device globals: no allocation allowed in kernel_launch)
__device__ __align__(16) float g_xwz[(size_t)BATCH * F];   // x@Wz + bz
__device__ __align__(16) float g_xwh[(size_t)BATCH * F];   // x@Wh + bh

// ---------------------------------------------------------------------------
// PTX helpers (protocol forms identical to the R9 run, which passed)
// ---------------------------------------------------------------------------
__device__ __forceinline__ uint32_t smem_u32(const void* p) {
    uint32_t a;
    asm("{ .reg .u64 t; cvta.to.shared.u64 t, %1; cvt.u32.u64 %0, t; }"
        : "=r"(a) : "l"(p));
    return a;
}
__device__ __forceinline__ unsigned long long fma2(
    unsigned long long a, unsigned long long b, unsigned long long c) {
    unsigned long long d;
    asm("fma.rn.f32x2 %0, %1, %2, %3;" : "=l"(d) : "l"(a), "l"(b), "l"(c));
    return d;
}
__device__ __forceinline__ unsigned long long add2(
    unsigned long long a, unsigned long long b) {
    unsigned long long d;
    asm("add.rn.f32x2 %0, %1, %2;" : "=l"(d) : "l"(a), "l"(b));
    return d;
}
__device__ __forceinline__ float pair_sum(unsigned long long p) {
    uint32_t lo, hi;
    asm("mov.b64 {%0, %1}, %2;" : "=r"(lo), "=r"(hi) : "l"(p));
    return __uint_as_float(lo) + __uint_as_float(hi);
}
__device__ __forceinline__ unsigned long long pack2f(float a0, float a1) {
    unsigned long long p;
    asm("mov.b64 %0, {%1, %2};" : "=l"(p)
        : "r"(__float_as_uint(a0)), "r"(__float_as_uint(a1)));
    return p;
}
__device__ __forceinline__ uint32_t mapa_rank(uint32_t laddr, int rank) {
    uint32_t r;
    asm("mapa.shared::cluster.u32 %0, %1, %2;" : "=r"(r) : "r"(laddr), "r"(rank));
    return r;
}
__device__ __forceinline__ void dsmem_store_u64(uint32_t raddr,
                                                unsigned long long v) {
    asm volatile("st.shared::cluster.u64 [%0], %1;"
                 :: "r"(raddr), "l"(v) : "memory");
}
__device__ __forceinline__ void st_release_flag(uint32_t raddr, unsigned v) {
    asm volatile("st.release.cluster.shared::cluster.u32 [%0], %1;"
                 :: "r"(raddr), "r"(v) : "memory");
}
__device__ __forceinline__ unsigned ld_acquire_flag(uint32_t laddr) {
    unsigned v;
    asm volatile("ld.acquire.cluster.shared::cta.u32 %0, [%1];"
                 : "=r"(v) : "r"(laddr) : "memory");
    return v;
}
__device__ __forceinline__ void lds_v2_u64(uint32_t addr,
                                           unsigned long long& a,
                                           unsigned long long& b) {
    asm volatile("ld.shared.v2.u64 {%0, %1}, [%2];"
                 : "=l"(a), "=l"(b) : "r"(addr));
}
__device__ __forceinline__ void cluster_arrive() {
    asm volatile("barrier.cluster.arrive.aligned;" ::: "memory");
}
__device__ __forceinline__ void cluster_wait() {
    asm volatile("barrier.cluster.wait.aligned;" ::: "memory");
}

// ---------------------------------------------------------------------------
// Phase 1: batched GEMM  C = A(16384x512) * W(512x512) + bias
// ---------------------------------------------------------------------------
#define BM 64
#define BN 64
#define BKK 16

__global__ void __launch_bounds__(256) gemm_kernel(
    const float* __restrict__ A,
    const float* __restrict__ Wz, const float* __restrict__ bz,
    const float* __restrict__ Wh, const float* __restrict__ bh)
{
    const float* B    = (blockIdx.z == 0) ? Wz : Wh;
    const float* bias = (blockIdx.z == 0) ? bz : bh;
    float*       C    = (blockIdx.z == 0) ? g_xwz : g_xwh;

    __shared__ float As[BKK][BM];
    __shared__ float Bs[BKK][BN];

    const int row0 = blockIdx.y * BM;
    const int col0 = blockIdx.x * BN;
    const int tid  = threadIdx.x;

    const int a_m = tid >> 2;
    const int a_k = (tid & 3) * 4;
    const int b_k = tid >> 4;
    const int b_n = (tid & 15) * 4;

    const int ty = tid >> 4;
    const int tx = tid & 15;

    float acc[4][4] = {};

    for (int k0 = 0; k0 < F; k0 += BKK) {
        float4 av = *(const float4*)(A + (size_t)(row0 + a_m) * F + k0 + a_k);
        As[a_k + 0][a_m] = av.x;
        As[a_k + 1][a_m] = av.y;
        As[a_k + 2][a_m] = av.z;
        As[a_k + 3][a_m] = av.w;
        float4 bv = *(const float4*)(B + (size_t)(k0 + b_k) * F + col0 + b_n);
        *(float4*)&Bs[b_k][b_n] = bv;
        __syncthreads();
#pragma unroll
        for (int k = 0; k < BKK; k++) {
            float ar[4], br[4];
            *(float4*)ar = *(const float4*)&As[k][ty * 4];
            *(float4*)br = *(const float4*)&Bs[k][tx * 4];
#pragma unroll
            for (int i = 0; i < 4; i++)
#pragma unroll
                for (int jj = 0; jj < 4; jj++)
                    acc[i][jj] = fmaf(ar[i], br[jj], acc[i][jj]);
        }
        __syncthreads();
    }

    float4 bv;
    bv.x = __ldg(&bias[col0 + tx * 4 + 0]);
    bv.y = __ldg(&bias[col0 + tx * 4 + 1]);
    bv.z = __ldg(&bias[col0 + tx * 4 + 2]);
    bv.w = __ldg(&bias[col0 + tx * 4 + 3]);
#pragma unroll
    for (int i = 0; i < 4; i++) {
        float4 o;
        o.x = acc[i][0] + bv.x;
        o.y = acc[i][1] + bv.y;
        o.z = acc[i][2] + bv.z;
        o.w = acc[i][3] + bv.w;
        *(float4*)(C + (size_t)(row0 + ty * 4 + i) * F + col0 + tx * 4) = o;
    }
}

// ---------------------------------------------------------------------------
// Phase 2: scan — R9's release-flag protocol, optimized.
//
// Layout: CTA b owns columns b*32..+31; warp w owns cols j0=b*32+2w (lanes
// 0-15) and j0+1 (lanes 16-31); lane l: rows (l&15)*32..+31 of its column,
// U in registers as packed f32x2.
//
// Per step t:
//  - all lanes compute the gate; mj (= m_{t-1}[mycol]) is REGISTER-CARRIED
//  - lane i<16 packs (mn_colj0, mn_colj0+1) via shfl_xor(mn,16) into ONE u64
//    and stores it to rank i's sval slot (256 remote stores/CTA, half of R9)
//  - __syncthreads; warp 0 lanes 0..15 publish flag=t+1 to rank=lane via
//    st.release.cluster (orders the CTA's scatter stores; R9-proven form)
//  - consumer lane polls ONE local 4B word (flag of producer hl) with
//    ld.acquire + 4-FMA backoff, then 8x lds_v2_u64 of naturally-paired
//    entries straight into fma2.
//
// sval entry k (u64) = cols {2k, 2k+1}; entries b*16+w are filled by warp w
// of CTA b. Swizzle: entry k (region r=k>>4, chunk c=(k>>1)&7, parity p=k&1)
// lives at physical entry r*16 + (((c ^ (r&7))<<1) | p). Consumer lane hl
// reads region hl chunk c at bank-group (c^hl)&7: the 16 lanes spread
// 2-per-group (2-phase minimum); lanes 16..31 duplicate (free broadcast).
//
// Slot-ring safety (4 slots; 2 suffice): flag_C >= t implies CTA C passed
// its step-(t-1) __syncthreads, i.e. all C's reads of step t-2 are done;
// a writer stores step t only after observing all flags >= t. Gang-
// scheduled cluster, local-only polling: no deadlock.
// ---------------------------------------------------------------------------
__global__ void __launch_bounds__(TPB, 1) scan_kernel(
    const float* __restrict__ Uz,
    const float* __restrict__ Uh,
    float* __restrict__ out)
{
    __shared__ __align__(16) unsigned long long sval[SLOTS][F / 2];  // 8 KB
    __shared__ unsigned eflag[16 * 8];     // 16 flags, 32 B apart

    const int b = blockIdx.x;              // cluster rank
    const int w = threadIdx.x >> 5;
    const int l = threadIdx.x & 31;
    const int hw = l >> 4;
    const int hl = l & 15;                 // producer rank for this lane's rows
    const int mycol = b * 32 + w * 2 + hw;
    const int rbase = hl * 32;
    const bool head = (hl == 0);           // one writer of out[] per column

    if (threadIdx.x < 16) eflag[threadIdx.x * 8] = 0u;
    __syncthreads();
    cluster_arrive();                      // all CTAs' flags zeroed before use

    // Preload packed U slices (rows rbase+2i, rbase+2i+1 of column mycol)
    unsigned long long uzp[16], uhp[16];
#pragma unroll
    for (int i = 0; i < 16; i++) {
        uzp[i] = pack2f(Uz[(size_t)(rbase + 2 * i) * F + mycol],
                        Uz[(size_t)(rbase + 2 * i + 1) * F + mycol]);
        uhp[i] = pack2f(Uh[(size_t)(rbase + 2 * i) * F + mycol],
                        Uh[(size_t)(rbase + 2 * i + 1) * F + mycol]);
    }

    // Producer physical entry for warp w of CTA b (see swizzle comment)
    const int kent  = b * 16 + w;
    const int pent  = b * 16 + ((((w >> 1) ^ (b & 7)) << 1) | (w & 1));
    (void)kent;
    uint32_t dstv[SLOTS];
#pragma unroll
    for (int s = 0; s < SLOTS; s++)
        dstv[s] = mapa_rank(smem_u32(&sval[s][0]) + pent * 8, l);  // rank = l (<16)
    uint32_t rflag = 0;
    if (w == 0 && l < 16)
        rflag = mapa_rank(smem_u32(&eflag[b * 8]), l);
    const uint32_t fl_own = smem_u32(&eflag[hl * 8]);  // my rows' producer

    cluster_wait();

    float xz_p = __ldg(&g_xwz[mycol]);     // x@W terms for t = 0
    float xh_p = __ldg(&g_xwh[mycol]);
    float mj = 0.f;                        // m_{t-1}[mycol], register-carried
    float fill = (float)(threadIdx.x + 1) * 1.0e-18f;   // backoff carrier

    for (int t = 0; t < BATCH; t++) {
        unsigned long long az0 = 0ull, az1 = 0ull, ah0 = 0ull, ah1 = 0ull;

        if (t > 0) {
            // Wait for producer hl to publish step t-1 (ONE local word).
            int rounds = 0;
            for (;;) {
                unsigned e = ld_acquire_flag(fl_own);
                if ((int)e >= t) break;
#pragma unroll
                for (int i = 0; i < 4; i++)
                    fill = fmaf(fill, 1.0000001f, 1.0e-30f);
                if (++rounds > 256) { __nanosleep(100); rounds = 128; }
            }
            // 8 swizzled 16B chunks -> 16 paired u64 -> fma2 directly
            const uint32_t regbase =
                smem_u32(&sval[(t - 1) & (SLOTS - 1)][0]) + hl * 128;
#pragma unroll
            for (int c = 0; c < 8; c++) {
                const uint32_t addr = regbase + (((c ^ (hl & 7)) & 7) << 4);
                unsigned long long m0, m1;
                lds_v2_u64(addr, m0, m1);
                // chunk c holds rows rbase+4c .. rbase+4c+3
                az0 = fma2(m0, uzp[2 * c],     az0);
                az1 = fma2(m1, uzp[2 * c + 1], az1);
                ah0 = fma2(m0, uhp[2 * c],     ah0);
                ah1 = fma2(m1, uhp[2 * c + 1], ah1);
            }
        }

        float az = pair_sum(add2(az0, az1));
        float ah = pair_sum(add2(ah0, ah1));
        // 4-level butterfly inside the half-warp: sum lands in every lane
#pragma unroll
        for (int s = 8; s > 0; s >>= 1) {
            az += __shfl_xor_sync(0xffffffffu, az, s);
            ah += __shfl_xor_sync(0xffffffffu, ah, s);
        }

        // All lanes compute the gate (mj register-carried)
        const float zp = az + xz_p;
        const float hp = ah + xh_p;
        const float z = __fdividef(1.f, 1.f + __expf(-zp));            // sigmoid
        const float h = 1.f - __fdividef(2.f, __expf(2.f * hp) + 1.f); // tanh
        const float mn = fmaf(z, h - mj, mj);

        if (head) out[(size_t)t * F + mycol] = mn;
        mj = mn;

        if (t + 1 < BATCH) {
            // Pack both columns of this warp into one u64 (halves stores)
            const float partner = __shfl_xor_sync(0xffffffffu, mn, 16);
            if (l < 16) {
                const unsigned long long pk = pack2f(mn, partner); // (even,odd)
                dsmem_store_u64(dstv[t & (SLOTS - 1)], pk);
            }
            __syncthreads();
            if (w == 0 && l < 16)
                st_release_flag(rflag, (unsigned)(t + 1));
            // Prefetch x@W for t+1 (off the critical path)
            xz_p = __ldg(&g_xwz[(size_t)(t + 1) * F + mycol]);
            xh_p = __ldg(&g_xwh[(size_t)(t + 1) * F + mycol]);
        }
    }

    // Keep the backoff chain live; condition can never hold.
    if (__float_as_uint(fill) == 0xdeadbeefu) out[0] = fill;

    // No CTA may exit while peers' DSMEM stores targeting it are in flight.
    cluster_arrive();
    cluster_wait();
}

// ---------------------------------------------------------------------------
// Launch: GEMMs -> single-cluster scan. All graph-capturable.
// ---------------------------------------------------------------------------
extern "C" void kernel_launch(void* const* d_in, const int* in_sizes, int n_in,
                              void* d_out, int out_size)
{
    const float* x  = (const float*)d_in[0];
    const float* Wz = (const float*)d_in[1];
    const float* Uz = (const float*)d_in[2];
    const float* bz = (const float*)d_in[3];
    const float* Wh = (const float*)d_in[4];
    const float* Uh = (const float*)d_in[5];
    const float* bh = (const float*)d_in[6];
    float* out = (float*)d_out;

    dim3 ggrid(F / BN, BATCH / BM, 2);   // 8 x 256 x 2
    gemm_kernel<<<ggrid, 256>>>(x, Wz, bz, Wh, bh);

    cudaFuncSetAttribute(scan_kernel,
                         cudaFuncAttributeNonPortableClusterSizeAllowed, 1);
    cudaLaunchConfig_t cfg = {};
    cfg.gridDim  = dim3(CLUSTER, 1, 1);
    cfg.blockDim = dim3(TPB, 1, 1);
    cfg.dynamicSmemBytes = 0;
    cfg.stream = 0;
    cudaLaunchAttribute attrs[1];
    attrs[0].id = cudaLaunchAttributeClusterDimension;
    attrs[0].val.clusterDim.x = CLUSTER;
    attrs[0].val.clusterDim.y = 1;
    attrs[0].val.clusterDim.z = 1;
    cfg.attrs = attrs;
    cfg.numAttrs = 1;
    cudaLaunchKernelEx(&cfg, scan_kernel, Uz, Uh, out);
}